// round 6
// baseline (speedup 1.0000x reference)
#include <cuda_runtime.h>
#include <cstdint>

#define MAXN 100000
#define MAXE 3200000
#define D 128
#define LN_EPS 1e-5f

// Scratch (device globals: allocation-free)
__device__ float g_H[(size_t)MAXN * D];    // post LN+Linear features
__device__ float g_agg[(size_t)MAXN * D];  // scatter accumulator
__device__ int   g_src[MAXE];
__device__ int   g_dst[MAXE];
__device__ int   g_is64;

// ---------------------------------------------------------------------------
// Index dtype probe: if buffer really holds int64 node ids, every 8-byte word
// is < 100000. If it holds int32, an int64 view combines two indices
// (lo + hi<<32) and is almost surely huge. 256 samples -> unambiguous.
// ---------------------------------------------------------------------------
__global__ void detect_kernel(const void* src, int E) {
    if (threadIdx.x == 0 && blockIdx.x == 0) {
        const unsigned long long* p = (const unsigned long long*)src;
        int n = 256;
        if (E / 2 < n) n = E / 2;
        int ok64 = 1;
        for (int i = 0; i < n; ++i) {
            if (p[i] >= (unsigned long long)MAXN) { ok64 = 0; break; }
        }
        g_is64 = ok64;
    }
}

__global__ void convert_kernel(const void* src, const void* dst, int E) {
    int is64 = g_is64;
    for (int i = blockIdx.x * blockDim.x + threadIdx.x; i < E;
         i += gridDim.x * blockDim.x) {
        int s, d;
        if (is64) {
            s = (int)((const long long*)src)[i];
            d = (int)((const long long*)dst)[i];
        } else {
            s = ((const int*)src)[i];
            d = ((const int*)dst)[i];
        }
        g_src[i] = s;
        g_dst[i] = d;
    }
}

// ---------------------------------------------------------------------------
// Zero the accumulator
// ---------------------------------------------------------------------------
__global__ void zero_kernel(int n4) {
    int i = blockIdx.x * blockDim.x + threadIdx.x;
    if (i < n4) ((float4*)g_agg)[i] = make_float4(0.f, 0.f, 0.f, 0.f);
}

// ---------------------------------------------------------------------------
// Fused LayerNorm + Linear (H = LN(X) @ W^T + b).
// W transposed into smem (stride 132 floats: float4-aligned reads, no read
// conflicts). Each warp processes tiles of 8 nodes: per d-step one W float4
// read is reused for 8 nodes (8x smem traffic amortization), keeping the
// kernel FFMA-bound instead of LDS-bound.
// ---------------------------------------------------------------------------
#define WSTRIDE 132
#define GEMM_SMEM (D * WSTRIDE * 4 + 8 * 8 * D * 4)   // W + per-warp h tiles

__global__ __launch_bounds__(256, 2)
void ln_gemm_kernel(const float* __restrict__ X,
                    const float* __restrict__ gamma,
                    const float* __restrict__ beta,
                    const float* __restrict__ W,
                    const float* __restrict__ bias,
                    int N) {
    extern __shared__ float smem[];
    float*  Wsh = smem;                               // [128][132]
    float4* hsh = (float4*)(smem + D * WSTRIDE);      // [8 warps][8 nodes][32]

    const int tid  = threadIdx.x;
    const int lane = tid & 31;
    const int warp = tid >> 5;

    // Load W transposed: Wsh[d*132 + o] = W[o*128 + d]
    for (int idx = tid; idx < D * D; idx += blockDim.x) {
        int o = idx >> 7;
        int d = idx & 127;
        Wsh[d * WSTRIDE + o] = W[idx];
    }
    __syncthreads();

    const float4 g4  = ((const float4*)gamma)[lane];
    const float4 be4 = ((const float4*)beta)[lane];
    const float4 b4  = ((const float4*)bias)[lane];
    const float4* X4 = (const float4*)X;
    float4* H4 = (float4*)g_H;

    const int nwarps = gridDim.x * (blockDim.x >> 5);
    const int gwarp  = blockIdx.x * (blockDim.x >> 5) + warp;
    const int ntiles = (N + 7) >> 3;

    for (int t = gwarp; t < ntiles; t += nwarps) {
        const int n0 = t << 3;

        __syncwarp();
        // -------- Phase A: LayerNorm for 8 nodes --------
        #pragma unroll
        for (int i = 0; i < 8; ++i) {
            int n = n0 + i;
            float4 x = make_float4(0.f, 0.f, 0.f, 0.f);
            if (n < N) x = X4[(size_t)n * 32 + lane];
            float s  = x.x + x.y + x.z + x.w;
            float ss = x.x * x.x + x.y * x.y + x.z * x.z + x.w * x.w;
            #pragma unroll
            for (int off = 16; off > 0; off >>= 1) {
                s  += __shfl_xor_sync(0xFFFFFFFFu, s,  off);
                ss += __shfl_xor_sync(0xFFFFFFFFu, ss, off);
            }
            float mu  = s * (1.f / 128.f);
            float var = ss * (1.f / 128.f) - mu * mu;
            float r   = rsqrtf(var + LN_EPS);
            float4 h;
            h.x = (x.x - mu) * r * g4.x + be4.x;
            h.y = (x.y - mu) * r * g4.y + be4.y;
            h.z = (x.z - mu) * r * g4.z + be4.z;
            h.w = (x.w - mu) * r * g4.w + be4.w;
            hsh[(warp * 8 + i) * 32 + lane] = h;
        }
        __syncwarp();

        // -------- Phase B: 8-node matvec, lane owns outputs 4*lane..+3 ----
        float4 acc[8];
        #pragma unroll
        for (int i = 0; i < 8; ++i) acc[i] = b4;

        #pragma unroll 2
        for (int dq = 0; dq < 32; ++dq) {
            float4 hv[8];
            #pragma unroll
            for (int i = 0; i < 8; ++i)
                hv[i] = hsh[(warp * 8 + i) * 32 + dq];  // broadcast

            const float* wb = Wsh + (dq << 2) * WSTRIDE;
            float4 w0 = *(const float4*)(wb + 4 * lane);
            float4 w1 = *(const float4*)(wb + WSTRIDE     + 4 * lane);
            float4 w2 = *(const float4*)(wb + 2 * WSTRIDE + 4 * lane);
            float4 w3 = *(const float4*)(wb + 3 * WSTRIDE + 4 * lane);

            #pragma unroll
            for (int i = 0; i < 8; ++i) {
                float4 a = acc[i];
                float4 h = hv[i];
                a.x += h.x * w0.x; a.y += h.x * w0.y; a.z += h.x * w0.z; a.w += h.x * w0.w;
                a.x += h.y * w1.x; a.y += h.y * w1.y; a.z += h.y * w1.z; a.w += h.y * w1.w;
                a.x += h.z * w2.x; a.y += h.z * w2.y; a.z += h.z * w2.z; a.w += h.z * w2.w;
                a.x += h.w * w3.x; a.y += h.w * w3.y; a.z += h.w * w3.z; a.w += h.w * w3.w;
                acc[i] = a;
            }
        }

        // -------- Phase C: store H rows --------
        #pragma unroll
        for (int i = 0; i < 8; ++i) {
            int n = n0 + i;
            if (n < N) H4[(size_t)n * 32 + lane] = acc[i];
        }
    }
}

// ---------------------------------------------------------------------------
// SpMM scatter: warp per edge, lane carries one float4 chunk of the row.
// red.global.add.v4.f32 = no-return 16B reduction (REDG path).
// ---------------------------------------------------------------------------
__device__ __forceinline__ void red_add_v4(float4* addr, float4 v) {
    asm volatile("red.global.add.v4.f32 [%0], {%1, %2, %3, %4};"
                 :: "l"(addr), "f"(v.x), "f"(v.y), "f"(v.z), "f"(v.w)
                 : "memory");
}

__global__ void spmm_kernel(const float* __restrict__ ew, int E) {
    int t    = blockIdx.x * blockDim.x + threadIdx.x;
    int e    = t >> 5;
    int lane = t & 31;
    if (e >= E) return;
    int   s = g_src[e];
    int   d = g_dst[e];
    float w = __ldg(ew + e);
    float4 h = ((const float4*)g_H)[(size_t)s * 32 + lane];
    float4 m = make_float4(h.x * w, h.y * w, h.z * w, h.w * w);
    red_add_v4(((float4*)g_agg) + (size_t)d * 32 + lane, m);
}

// ---------------------------------------------------------------------------
// out = relu(agg) + X
// ---------------------------------------------------------------------------
__global__ void epilogue_kernel(const float* __restrict__ X,
                                float* __restrict__ out, int n4) {
    int i = blockIdx.x * blockDim.x + threadIdx.x;
    if (i >= n4) return;
    float4 a = ((const float4*)g_agg)[i];
    float4 x = ((const float4*)X)[i];
    float4 o;
    o.x = fmaxf(a.x, 0.f) + x.x;
    o.y = fmaxf(a.y, 0.f) + x.y;
    o.z = fmaxf(a.z, 0.f) + x.z;
    o.w = fmaxf(a.w, 0.f) + x.w;
    ((float4*)out)[i] = o;
}

// ---------------------------------------------------------------------------
// inputs: 0:X 1:edge_src 2:edge_dst 3:edge_w 4:ln_gamma 5:ln_beta 6:W 7:b
// ---------------------------------------------------------------------------
extern "C" void kernel_launch(void* const* d_in, const int* in_sizes, int n_in,
                              void* d_out, int out_size) {
    const float* X     = (const float*)d_in[0];
    const void*  esrc  = d_in[1];
    const void*  edst  = d_in[2];
    const float* ew    = (const float*)d_in[3];
    const float* gamma = (const float*)d_in[4];
    const float* beta  = (const float*)d_in[5];
    const float* W     = (const float*)d_in[6];
    const float* bias  = (const float*)d_in[7];
    float* out = (float*)d_out;

    const int N  = in_sizes[0] / D;
    const int E  = in_sizes[1];
    const int n4 = N * (D / 4);

    // 1. index dtype probe + convert to int32
    detect_kernel<<<1, 32>>>(esrc, E);
    convert_kernel<<<4096, 256>>>(esrc, edst, E);

    // 2. zero accumulator
    zero_kernel<<<(n4 + 255) / 256, 256>>>(n4);

    // 3. fused LN + Linear
    cudaFuncSetAttribute(ln_gemm_kernel,
                         cudaFuncAttributeMaxDynamicSharedMemorySize,
                         GEMM_SMEM);
    ln_gemm_kernel<<<296, 256, GEMM_SMEM>>>(X, gamma, beta, W, bias, N);

    // 4. edge scatter
    {
        long long threads = (long long)E * 32;
        int blocks = (int)((threads + 255) / 256);
        spmm_kernel<<<blocks, 256>>>(ew, E);
    }

    // 5. relu + residual
    epilogue_kernel<<<(n4 + 255) / 256, 256>>>(X, out, n4);
}

// round 10
// speedup vs baseline: 1.1731x; 1.1731x over previous
#include <cuda_runtime.h>
#include <cstdint>

#define MAXN 100000
#define MAXE 3200000
#define D 128
#define LN_EPS 1e-5f

// Scratch (device globals: allocation-free)
__device__ float g_H[(size_t)MAXN * D];      // post LN+Linear features
__device__ int   g_deg[MAXN + 1];            // per-dst degree histogram
__device__ int   g_off[MAXN + 1];            // CSR row offsets
__device__ int   g_cursor[MAXN];             // fill cursors for scatter
__device__ int   g_csr_src[MAXE];            // CSR column (src node)
__device__ float g_csr_w[MAXE];              // CSR edge weight
__device__ int   g_is64;

// ---------------------------------------------------------------------------
// Index dtype probe: real int64 node ids are all < 100000; an int32 buffer
// viewed as int64 combines two indices and is almost surely >= 2^32.
// ---------------------------------------------------------------------------
__global__ void detect_kernel(const void* src, int E) {
    if (threadIdx.x == 0 && blockIdx.x == 0) {
        const unsigned long long* p = (const unsigned long long*)src;
        int n = 256;
        if (E / 2 < n) n = E / 2;
        int ok64 = 1;
        for (int i = 0; i < n; ++i) {
            if (p[i] >= (unsigned long long)MAXN) { ok64 = 0; break; }
        }
        g_is64 = ok64;
    }
}

__device__ __forceinline__ int load_idx(const void* p, int i, int is64) {
    return is64 ? (int)((const long long*)p)[i] : ((const int*)p)[i];
}

// ---------------------------------------------------------------------------
// CSR build: zero degrees -> histogram -> exclusive scan -> scatter
// ---------------------------------------------------------------------------
__global__ void zero_deg_kernel(int N) {
    int i = blockIdx.x * blockDim.x + threadIdx.x;
    if (i <= N) g_deg[i] = 0;
}

__global__ void hist_kernel(const void* edst, int E) {
    int is64 = g_is64;
    for (int i = blockIdx.x * blockDim.x + threadIdx.x; i < E;
         i += gridDim.x * blockDim.x) {
        int d = load_idx(edst, i, is64);
        atomicAdd(&g_deg[d], 1);
    }
}

// Single-block exclusive scan over N counters (chunked + Hillis-Steele).
__global__ void scan_kernel(int N) {
    __shared__ int sums[1024];
    const int t = threadIdx.x;
    const int chunk = (N + 1023) >> 10;
    const int start = t * chunk;
    const int end   = min(start + chunk, N);

    int s = 0;
    for (int i = start; i < end; ++i) s += g_deg[i];
    sums[t] = s;
    __syncthreads();

    #pragma unroll
    for (int off = 1; off < 1024; off <<= 1) {
        int v = (t >= off) ? sums[t - off] : 0;
        __syncthreads();
        sums[t] += v;
        __syncthreads();
    }

    int base = (t == 0) ? 0 : sums[t - 1];
    for (int i = start; i < end; ++i) {
        int d = g_deg[i];
        g_off[i]    = base;
        g_cursor[i] = base;
        base += d;
    }
    if (t == 1023) g_off[N] = base;   // == E
}

__global__ void scatter_kernel(const void* esrc, const void* edst,
                               const float* __restrict__ ew, int E) {
    int is64 = g_is64;
    for (int i = blockIdx.x * blockDim.x + threadIdx.x; i < E;
         i += gridDim.x * blockDim.x) {
        int s = load_idx(esrc, i, is64);
        int d = load_idx(edst, i, is64);
        int pos = atomicAdd(&g_cursor[d], 1);
        g_csr_src[pos] = s;
        g_csr_w[pos]   = ew[i];
    }
}

// ---------------------------------------------------------------------------
// Fused LayerNorm + Linear (H = LN(X) @ W^T + b). Unchanged from R5
// (near FFMA/LDS roofline at 85us).
// ---------------------------------------------------------------------------
#define WSTRIDE 132
#define GEMM_SMEM (D * WSTRIDE * 4 + 8 * 8 * D * 4)

__global__ __launch_bounds__(256, 2)
void ln_gemm_kernel(const float* __restrict__ X,
                    const float* __restrict__ gamma,
                    const float* __restrict__ beta,
                    const float* __restrict__ W,
                    const float* __restrict__ bias,
                    int N) {
    extern __shared__ float smem[];
    float*  Wsh = smem;                               // [128][132]
    float4* hsh = (float4*)(smem + D * WSTRIDE);      // [8 warps][8 nodes][32]

    const int tid  = threadIdx.x;
    const int lane = tid & 31;
    const int warp = tid >> 5;

    for (int idx = tid; idx < D * D; idx += blockDim.x) {
        int o = idx >> 7;
        int d = idx & 127;
        Wsh[d * WSTRIDE + o] = W[idx];
    }
    __syncthreads();

    const float4 g4  = ((const float4*)gamma)[lane];
    const float4 be4 = ((const float4*)beta)[lane];
    const float4 b4  = ((const float4*)bias)[lane];
    const float4* X4 = (const float4*)X;
    float4* H4 = (float4*)g_H;

    const int nwarps = gridDim.x * (blockDim.x >> 5);
    const int gwarp  = blockIdx.x * (blockDim.x >> 5) + warp;
    const int ntiles = (N + 7) >> 3;

    for (int t = gwarp; t < ntiles; t += nwarps) {
        const int n0 = t << 3;

        __syncwarp();
        #pragma unroll
        for (int i = 0; i < 8; ++i) {
            int n = n0 + i;
            float4 x = make_float4(0.f, 0.f, 0.f, 0.f);
            if (n < N) x = X4[(size_t)n * 32 + lane];
            float s  = x.x + x.y + x.z + x.w;
            float ss = x.x * x.x + x.y * x.y + x.z * x.z + x.w * x.w;
            #pragma unroll
            for (int off = 16; off > 0; off >>= 1) {
                s  += __shfl_xor_sync(0xFFFFFFFFu, s,  off);
                ss += __shfl_xor_sync(0xFFFFFFFFu, ss, off);
            }
            float mu  = s * (1.f / 128.f);
            float var = ss * (1.f / 128.f) - mu * mu;
            float r   = rsqrtf(var + LN_EPS);
            float4 h;
            h.x = (x.x - mu) * r * g4.x + be4.x;
            h.y = (x.y - mu) * r * g4.y + be4.y;
            h.z = (x.z - mu) * r * g4.z + be4.z;
            h.w = (x.w - mu) * r * g4.w + be4.w;
            hsh[(warp * 8 + i) * 32 + lane] = h;
        }
        __syncwarp();

        float4 acc[8];
        #pragma unroll
        for (int i = 0; i < 8; ++i) acc[i] = b4;

        #pragma unroll 2
        for (int dq = 0; dq < 32; ++dq) {
            float4 hv[8];
            #pragma unroll
            for (int i = 0; i < 8; ++i)
                hv[i] = hsh[(warp * 8 + i) * 32 + dq];

            const float* wb = Wsh + (dq << 2) * WSTRIDE;
            float4 w0 = *(const float4*)(wb + 4 * lane);
            float4 w1 = *(const float4*)(wb + WSTRIDE     + 4 * lane);
            float4 w2 = *(const float4*)(wb + 2 * WSTRIDE + 4 * lane);
            float4 w3 = *(const float4*)(wb + 3 * WSTRIDE + 4 * lane);

            #pragma unroll
            for (int i = 0; i < 8; ++i) {
                float4 a = acc[i];
                float4 h = hv[i];
                a.x += h.x * w0.x; a.y += h.x * w0.y; a.z += h.x * w0.z; a.w += h.x * w0.w;
                a.x += h.y * w1.x; a.y += h.y * w1.y; a.z += h.y * w1.z; a.w += h.y * w1.w;
                a.x += h.z * w2.x; a.y += h.z * w2.y; a.z += h.z * w2.z; a.w += h.z * w2.w;
                a.x += h.w * w3.x; a.y += h.w * w3.y; a.z += h.w * w3.z; a.w += h.w * w3.w;
                acc[i] = a;
            }
        }

        #pragma unroll
        for (int i = 0; i < 8; ++i) {
            int n = n0 + i;
            if (n < N) H4[(size_t)n * 32 + lane] = acc[i];
        }
    }
}

// ---------------------------------------------------------------------------
// CSR aggregation, fused with relu + residual.
// Warp per dst node: lane owns one 16B chunk of the 512B row. Edge entries
// loaded cooperatively (one coalesced load per 32 edges), broadcast via shfl.
// 4-wide unroll gives 4 independent in-flight gathers per warp.
// ---------------------------------------------------------------------------
__global__ __launch_bounds__(256)
void agg_kernel(const float* __restrict__ X, float* __restrict__ out, int N) {
    const int w    = (blockIdx.x * blockDim.x + threadIdx.x) >> 5;
    const int lane = threadIdx.x & 31;
    if (w >= N) return;

    const int beg = g_off[w];
    const int end = g_off[w + 1];
    const float4* H4 = (const float4*)g_H;

    float4 acc = make_float4(0.f, 0.f, 0.f, 0.f);

    for (int j0 = beg; j0 < end; j0 += 32) {
        const int j = j0 + lane;
        int   s  = 0;
        float ww = 0.f;
        if (j < end) { s = __ldg(&g_csr_src[j]); ww = __ldg(&g_csr_w[j]); }
        const int cnt = min(32, end - j0);

        int k = 0;
        for (; k + 4 <= cnt; k += 4) {
            int   s0 = __shfl_sync(0xFFFFFFFFu, s,  k);
            int   s1 = __shfl_sync(0xFFFFFFFFu, s,  k + 1);
            int   s2 = __shfl_sync(0xFFFFFFFFu, s,  k + 2);
            int   s3 = __shfl_sync(0xFFFFFFFFu, s,  k + 3);
            float w0 = __shfl_sync(0xFFFFFFFFu, ww, k);
            float w1 = __shfl_sync(0xFFFFFFFFu, ww, k + 1);
            float w2 = __shfl_sync(0xFFFFFFFFu, ww, k + 2);
            float w3 = __shfl_sync(0xFFFFFFFFu, ww, k + 3);
            float4 h0 = H4[(size_t)s0 * 32 + lane];
            float4 h1 = H4[(size_t)s1 * 32 + lane];
            float4 h2 = H4[(size_t)s2 * 32 + lane];
            float4 h3 = H4[(size_t)s3 * 32 + lane];
            acc.x += w0 * h0.x; acc.y += w0 * h0.y; acc.z += w0 * h0.z; acc.w += w0 * h0.w;
            acc.x += w1 * h1.x; acc.y += w1 * h1.y; acc.z += w1 * h1.z; acc.w += w1 * h1.w;
            acc.x += w2 * h2.x; acc.y += w2 * h2.y; acc.z += w2 * h2.z; acc.w += w2 * h2.w;
            acc.x += w3 * h3.x; acc.y += w3 * h3.y; acc.z += w3 * h3.z; acc.w += w3 * h3.w;
        }
        for (; k < cnt; ++k) {
            int   sk = __shfl_sync(0xFFFFFFFFu, s,  k);
            float wk = __shfl_sync(0xFFFFFFFFu, ww, k);
            float4 h = H4[(size_t)sk * 32 + lane];
            acc.x += wk * h.x; acc.y += wk * h.y;
            acc.z += wk * h.z; acc.w += wk * h.w;
        }
    }

    float4 x = ((const float4*)X)[(size_t)w * 32 + lane];
    float4 o;
    o.x = fmaxf(acc.x, 0.f) + x.x;
    o.y = fmaxf(acc.y, 0.f) + x.y;
    o.z = fmaxf(acc.z, 0.f) + x.z;
    o.w = fmaxf(acc.w, 0.f) + x.w;
    ((float4*)out)[(size_t)w * 32 + lane] = o;
}

// ---------------------------------------------------------------------------
// inputs: 0:X 1:edge_src 2:edge_dst 3:edge_w 4:ln_gamma 5:ln_beta 6:W 7:b
// ---------------------------------------------------------------------------
extern "C" void kernel_launch(void* const* d_in, const int* in_sizes, int n_in,
                              void* d_out, int out_size) {
    const float* X     = (const float*)d_in[0];
    const void*  esrc  = d_in[1];
    const void*  edst  = d_in[2];
    const float* ew    = (const float*)d_in[3];
    const float* gamma = (const float*)d_in[4];
    const float* beta  = (const float*)d_in[5];
    const float* W     = (const float*)d_in[6];
    const float* bias  = (const float*)d_in[7];
    float* out = (float*)d_out;

    const int N = in_sizes[0] / D;
    const int E = in_sizes[1];

    // 1. index dtype probe
    detect_kernel<<<1, 32>>>(esrc, E);

    // 2. CSR build (by destination)
    zero_deg_kernel<<<(N + 256) / 256, 256>>>(N);
    hist_kernel<<<2048, 256>>>(edst, E);
    scan_kernel<<<1, 1024>>>(N);
    scatter_kernel<<<2048, 256>>>(esrc, edst, ew, E);

    // 3. fused LN + Linear
    cudaFuncSetAttribute(ln_gemm_kernel,
                         cudaFuncAttributeMaxDynamicSharedMemorySize,
                         GEMM_SMEM);
    ln_gemm_kernel<<<296, 256, GEMM_SMEM>>>(X, gamma, beta, W, bias, N);

    // 4. CSR aggregation fused with relu + residual
    agg_kernel<<<(N + 7) / 8, 256>>>(X, out, N);
}

// round 13
// speedup vs baseline: 1.8950x; 1.6154x over previous
#include <cuda_runtime.h>
#include <cuda_fp16.h>
#include <cstdint>

#define MAXN 100000
#define MAXE 3200000
#define D 128
#define LN_EPS 1e-5f

// Scratch (device globals: allocation-free)
__device__ __half g_H[(size_t)MAXN * D];     // post LN+Linear features (fp16)
__device__ int    g_deg[MAXN + 1];           // per-dst degree histogram
__device__ int    g_off[MAXN + 1];           // CSR row offsets
__device__ int    g_cursor[MAXN];            // fill cursors for scatter
__device__ int    g_csr_src[MAXE];           // CSR column (src node)
__device__ float  g_csr_w[MAXE];             // CSR edge weight
__device__ int    g_bsum[128];               // per-block partial sums for scan
__device__ int    g_is64;

// ---------------------------------------------------------------------------
// Index dtype probe (parallel): real int64 ids are all < 100000; an int32
// buffer viewed as int64 packs two indices and is almost surely >= 2^32.
// ---------------------------------------------------------------------------
__global__ void detect_kernel(const void* src, int E) {
    int n = E / 2;
    if (n > 256) n = 256;
    int t = threadIdx.x;
    int bad = 0;
    if (t < n)
        bad = (((const unsigned long long*)src)[t] >= (unsigned long long)MAXN);
    int any = __syncthreads_or(bad);
    if (t == 0) g_is64 = !any;
}

__device__ __forceinline__ int load_idx(const void* p, int i, int is64) {
    return is64 ? (int)((const long long*)p)[i] : ((const int*)p)[i];
}

// ---------------------------------------------------------------------------
// CSR build: zero -> histogram -> hierarchical scan -> scatter
// ---------------------------------------------------------------------------
__global__ void zero_deg_kernel(int N) {
    int i = blockIdx.x * blockDim.x + threadIdx.x;
    if (i <= N) g_deg[i] = 0;
}

__global__ void hist_kernel(const void* edst, int E) {
    int is64 = g_is64;
    for (int i = blockIdx.x * blockDim.x + threadIdx.x; i < E;
         i += gridDim.x * blockDim.x) {
        int d = load_idx(edst, i, is64);
        atomicAdd(&g_deg[d], 1);
    }
}

// Scan stage 1: per-block sum of 1024 degree entries.
__global__ void scan1_kernel(int N) {
    __shared__ int sh[1024];
    int t = threadIdx.x;
    int i = blockIdx.x * 1024 + t;
    sh[t] = (i < N) ? g_deg[i] : 0;
    __syncthreads();
    #pragma unroll
    for (int off = 512; off > 0; off >>= 1) {
        if (t < off) sh[t] += sh[t + off];
        __syncthreads();
    }
    if (t == 0) g_bsum[blockIdx.x] = sh[0];
}

// Scan stage 2: exclusive scan of <=128 block sums (one tiny block).
__global__ void scan2_kernel(int nb, int N, int E) {
    __shared__ int sh[128];
    int t = threadIdx.x;
    int v = (t < nb) ? g_bsum[t] : 0;
    sh[t] = v;
    __syncthreads();
    #pragma unroll
    for (int off = 1; off < 128; off <<= 1) {
        int u = (t >= off) ? sh[t - off] : 0;
        __syncthreads();
        sh[t] += u;
        __syncthreads();
    }
    if (t < nb) g_bsum[t] = sh[t] - v;   // exclusive
    if (t == 0) g_off[N] = E;
}

// Scan stage 3: per-block inclusive scan + base -> offsets & cursors.
__global__ void scan3_kernel(int N) {
    __shared__ int sh[1024];
    int t = threadIdx.x;
    int i = blockIdx.x * 1024 + t;
    int v = (i < N) ? g_deg[i] : 0;
    sh[t] = v;
    __syncthreads();
    #pragma unroll
    for (int off = 1; off < 1024; off <<= 1) {
        int u = (t >= off) ? sh[t - off] : 0;
        __syncthreads();
        sh[t] += u;
        __syncthreads();
    }
    if (i < N) {
        int excl = g_bsum[blockIdx.x] + sh[t] - v;
        g_off[i]    = excl;
        g_cursor[i] = excl;
    }
}

__global__ void scatter_kernel(const void* esrc, const void* edst,
                               const float* __restrict__ ew, int E) {
    int is64 = g_is64;
    for (int i = blockIdx.x * blockDim.x + threadIdx.x; i < E;
         i += gridDim.x * blockDim.x) {
        int s = load_idx(esrc, i, is64);
        int d = load_idx(edst, i, is64);
        int pos = atomicAdd(&g_cursor[d], 1);
        g_csr_src[pos] = s;
        g_csr_w[pos]   = ew[i];
    }
}

// ---------------------------------------------------------------------------
// Fused LayerNorm + Linear (H = LN(X) @ W^T + b), H stored fp16.
// ---------------------------------------------------------------------------
#define WSTRIDE 132
#define GEMM_SMEM (D * WSTRIDE * 4 + 8 * 8 * D * 4)

__global__ __launch_bounds__(256, 2)
void ln_gemm_kernel(const float* __restrict__ X,
                    const float* __restrict__ gamma,
                    const float* __restrict__ beta,
                    const float* __restrict__ W,
                    const float* __restrict__ bias,
                    int N) {
    extern __shared__ float smem[];
    float*  Wsh = smem;                               // [128][132]
    float4* hsh = (float4*)(smem + D * WSTRIDE);      // [8 warps][8 nodes][32]

    const int tid  = threadIdx.x;
    const int lane = tid & 31;
    const int warp = tid >> 5;

    for (int idx = tid; idx < D * D; idx += blockDim.x) {
        int o = idx >> 7;
        int d = idx & 127;
        Wsh[d * WSTRIDE + o] = W[idx];
    }
    __syncthreads();

    const float4 g4  = ((const float4*)gamma)[lane];
    const float4 be4 = ((const float4*)beta)[lane];
    const float4 b4  = ((const float4*)bias)[lane];
    const float4* X4 = (const float4*)X;
    uint2* H2 = (uint2*)g_H;   // 32 x 8B chunks per row

    const int nwarps = gridDim.x * (blockDim.x >> 5);
    const int gwarp  = blockIdx.x * (blockDim.x >> 5) + warp;
    const int ntiles = (N + 7) >> 3;

    for (int t = gwarp; t < ntiles; t += nwarps) {
        const int n0 = t << 3;

        __syncwarp();
        #pragma unroll
        for (int i = 0; i < 8; ++i) {
            int n = n0 + i;
            float4 x = make_float4(0.f, 0.f, 0.f, 0.f);
            if (n < N) x = X4[(size_t)n * 32 + lane];
            float s  = x.x + x.y + x.z + x.w;
            float ss = x.x * x.x + x.y * x.y + x.z * x.z + x.w * x.w;
            #pragma unroll
            for (int off = 16; off > 0; off >>= 1) {
                s  += __shfl_xor_sync(0xFFFFFFFFu, s,  off);
                ss += __shfl_xor_sync(0xFFFFFFFFu, ss, off);
            }
            float mu  = s * (1.f / 128.f);
            float var = ss * (1.f / 128.f) - mu * mu;
            float r   = rsqrtf(var + LN_EPS);
            float4 h;
            h.x = (x.x - mu) * r * g4.x + be4.x;
            h.y = (x.y - mu) * r * g4.y + be4.y;
            h.z = (x.z - mu) * r * g4.z + be4.z;
            h.w = (x.w - mu) * r * g4.w + be4.w;
            hsh[(warp * 8 + i) * 32 + lane] = h;
        }
        __syncwarp();

        float4 acc[8];
        #pragma unroll
        for (int i = 0; i < 8; ++i) acc[i] = b4;

        #pragma unroll 2
        for (int dq = 0; dq < 32; ++dq) {
            float4 hv[8];
            #pragma unroll
            for (int i = 0; i < 8; ++i)
                hv[i] = hsh[(warp * 8 + i) * 32 + dq];

            const float* wb = Wsh + (dq << 2) * WSTRIDE;
            float4 w0 = *(const float4*)(wb + 4 * lane);
            float4 w1 = *(const float4*)(wb + WSTRIDE     + 4 * lane);
            float4 w2 = *(const float4*)(wb + 2 * WSTRIDE + 4 * lane);
            float4 w3 = *(const float4*)(wb + 3 * WSTRIDE + 4 * lane);

            #pragma unroll
            for (int i = 0; i < 8; ++i) {
                float4 a = acc[i];
                float4 h = hv[i];
                a.x += h.x * w0.x; a.y += h.x * w0.y; a.z += h.x * w0.z; a.w += h.x * w0.w;
                a.x += h.y * w1.x; a.y += h.y * w1.y; a.z += h.y * w1.z; a.w += h.y * w1.w;
                a.x += h.z * w2.x; a.y += h.z * w2.y; a.z += h.z * w2.z; a.w += h.z * w2.w;
                a.x += h.w * w3.x; a.y += h.w * w3.y; a.z += h.w * w3.z; a.w += h.w * w3.w;
                acc[i] = a;
            }
        }

        #pragma unroll
        for (int i = 0; i < 8; ++i) {
            int n = n0 + i;
            if (n < N) {
                __half2 p0 = __floats2half2_rn(acc[i].x, acc[i].y);
                __half2 p1 = __floats2half2_rn(acc[i].z, acc[i].w);
                uint2 u;
                u.x = *(const unsigned*)&p0;
                u.y = *(const unsigned*)&p1;
                H2[(size_t)n * 32 + lane] = u;
            }
        }
    }
}

// ---------------------------------------------------------------------------
// CSR aggregation (fp16 gather), fused with relu + residual.
// Warp per dst node: lane owns one 8B chunk (4 halves) of the 256B row.
// ---------------------------------------------------------------------------
__global__ __launch_bounds__(256)
void agg_kernel(const float* __restrict__ X, float* __restrict__ out, int N) {
    const int w    = (blockIdx.x * blockDim.x + threadIdx.x) >> 5;
    const int lane = threadIdx.x & 31;
    if (w >= N) return;

    const int beg = g_off[w];
    const int end = g_off[w + 1];
    const uint2* H2 = (const uint2*)g_H;

    float4 acc = make_float4(0.f, 0.f, 0.f, 0.f);

    for (int j0 = beg; j0 < end; j0 += 32) {
        const int j = j0 + lane;
        int   s  = 0;
        float ww = 0.f;
        if (j < end) { s = __ldg(&g_csr_src[j]); ww = __ldg(&g_csr_w[j]); }
        const int cnt = min(32, end - j0);

        int k = 0;
        for (; k + 4 <= cnt; k += 4) {
            int   s0 = __shfl_sync(0xFFFFFFFFu, s,  k);
            int   s1 = __shfl_sync(0xFFFFFFFFu, s,  k + 1);
            int   s2 = __shfl_sync(0xFFFFFFFFu, s,  k + 2);
            int   s3 = __shfl_sync(0xFFFFFFFFu, s,  k + 3);
            float w0 = __shfl_sync(0xFFFFFFFFu, ww, k);
            float w1 = __shfl_sync(0xFFFFFFFFu, ww, k + 1);
            float w2 = __shfl_sync(0xFFFFFFFFu, ww, k + 2);
            float w3 = __shfl_sync(0xFFFFFFFFu, ww, k + 3);
            uint2 u0 = H2[(size_t)s0 * 32 + lane];
            uint2 u1 = H2[(size_t)s1 * 32 + lane];
            uint2 u2 = H2[(size_t)s2 * 32 + lane];
            uint2 u3 = H2[(size_t)s3 * 32 + lane];
            float2 a0 = __half22float2(*(const __half2*)&u0.x);
            float2 b0 = __half22float2(*(const __half2*)&u0.y);
            float2 a1 = __half22float2(*(const __half2*)&u1.x);
            float2 b1 = __half22float2(*(const __half2*)&u1.y);
            float2 a2 = __half22float2(*(const __half2*)&u2.x);
            float2 b2 = __half22float2(*(const __half2*)&u2.y);
            float2 a3 = __half22float2(*(const __half2*)&u3.x);
            float2 b3 = __half22float2(*(const __half2*)&u3.y);
            acc.x += w0 * a0.x; acc.y += w0 * a0.y; acc.z += w0 * b0.x; acc.w += w0 * b0.y;
            acc.x += w1 * a1.x; acc.y += w1 * a1.y; acc.z += w1 * b1.x; acc.w += w1 * b1.y;
            acc.x += w2 * a2.x; acc.y += w2 * a2.y; acc.z += w2 * b2.x; acc.w += w2 * b2.y;
            acc.x += w3 * a3.x; acc.y += w3 * a3.y; acc.z += w3 * b3.x; acc.w += w3 * b3.y;
        }
        for (; k < cnt; ++k) {
            int   sk = __shfl_sync(0xFFFFFFFFu, s,  k);
            float wk = __shfl_sync(0xFFFFFFFFu, ww, k);
            uint2 u = H2[(size_t)sk * 32 + lane];
            float2 a = __half22float2(*(const __half2*)&u.x);
            float2 b = __half22float2(*(const __half2*)&u.y);
            acc.x += wk * a.x; acc.y += wk * a.y;
            acc.z += wk * b.x; acc.w += wk * b.y;
        }
    }

    float4 x = ((const float4*)X)[(size_t)w * 32 + lane];
    float4 o;
    o.x = fmaxf(acc.x, 0.f) + x.x;
    o.y = fmaxf(acc.y, 0.f) + x.y;
    o.z = fmaxf(acc.z, 0.f) + x.z;
    o.w = fmaxf(acc.w, 0.f) + x.w;
    ((float4*)out)[(size_t)w * 32 + lane] = o;
}

// ---------------------------------------------------------------------------
// inputs: 0:X 1:edge_src 2:edge_dst 3:edge_w 4:ln_gamma 5:ln_beta 6:W 7:b
// ---------------------------------------------------------------------------
extern "C" void kernel_launch(void* const* d_in, const int* in_sizes, int n_in,
                              void* d_out, int out_size) {
    const float* X     = (const float*)d_in[0];
    const void*  esrc  = d_in[1];
    const void*  edst  = d_in[2];
    const float* ew    = (const float*)d_in[3];
    const float* gamma = (const float*)d_in[4];
    const float* beta  = (const float*)d_in[5];
    const float* W     = (const float*)d_in[6];
    const float* bias  = (const float*)d_in[7];
    float* out = (float*)d_out;

    const int N  = in_sizes[0] / D;
    const int E  = in_sizes[1];
    const int NB = (N + 1023) / 1024;   // <= 128 for N <= 131072

    // 1. index dtype probe
    detect_kernel<<<1, 256>>>(esrc, E);

    // 2. CSR build (by destination)
    zero_deg_kernel<<<(N + 256) / 256, 256>>>(N);
    hist_kernel<<<2048, 256>>>(edst, E);
    scan1_kernel<<<NB, 1024>>>(N);
    scan2_kernel<<<1, 128>>>(NB, N, E);
    scan3_kernel<<<NB, 1024>>>(N);
    scatter_kernel<<<2048, 256>>>(esrc, edst, ew, E);

    // 3. fused LN + Linear (H in fp16)
    cudaFuncSetAttribute(ln_gemm_kernel,
                         cudaFuncAttributeMaxDynamicSharedMemorySize,
                         GEMM_SMEM);
    ln_gemm_kernel<<<296, 256, GEMM_SMEM>>>(X, gamma, beta, W, bias, N);

    // 4. CSR aggregation fused with relu + residual
    agg_kernel<<<(N + 7) / 8, 256>>>(X, out, N);
}

// round 14
// speedup vs baseline: 2.3598x; 1.2453x over previous
#include <cuda_runtime.h>
#include <cuda_fp16.h>
#include <cstdint>

#define MAXN 100000
#define MAXE 3200000
#define D 128
#define LN_EPS 1e-5f

// Scratch (device globals: allocation-free)
__device__ __half g_H[(size_t)MAXN * D];     // post LN+Linear features (fp16)
__device__ __half g_Wh[D * D];               // W in fp16
__device__ int    g_deg[MAXN + 1];
__device__ int    g_off[MAXN + 1];
__device__ int    g_cursor[MAXN];
__device__ int    g_csr_src[MAXE];
__device__ float  g_csr_w[MAXE];
__device__ int    g_bsum[128];
__device__ int    g_is64;

// ---------------------------------------------------------------------------
// Index dtype probe
// ---------------------------------------------------------------------------
__global__ void detect_kernel(const void* src, int E) {
    int n = E / 2;
    if (n > 256) n = 256;
    int t = threadIdx.x;
    int bad = 0;
    if (t < n)
        bad = (((const unsigned long long*)src)[t] >= (unsigned long long)MAXN);
    int any = __syncthreads_or(bad);
    if (t == 0) g_is64 = !any;
}

__device__ __forceinline__ int load_idx(const void* p, int i, int is64) {
    return is64 ? (int)((const long long*)p)[i] : ((const int*)p)[i];
}

// ---------------------------------------------------------------------------
// CSR build: zero -> histogram -> hierarchical scan -> scatter
// ---------------------------------------------------------------------------
__global__ void zero_deg_kernel(int N) {
    int i = blockIdx.x * blockDim.x + threadIdx.x;
    if (i <= N) g_deg[i] = 0;
}

__global__ void hist_kernel(const void* edst, int E) {
    int is64 = g_is64;
    for (int i = blockIdx.x * blockDim.x + threadIdx.x; i < E;
         i += gridDim.x * blockDim.x) {
        int d = load_idx(edst, i, is64);
        atomicAdd(&g_deg[d], 1);
    }
}

__global__ void scan1_kernel(int N) {
    __shared__ int sh[1024];
    int t = threadIdx.x;
    int i = blockIdx.x * 1024 + t;
    sh[t] = (i < N) ? g_deg[i] : 0;
    __syncthreads();
    #pragma unroll
    for (int off = 512; off > 0; off >>= 1) {
        if (t < off) sh[t] += sh[t + off];
        __syncthreads();
    }
    if (t == 0) g_bsum[blockIdx.x] = sh[0];
}

__global__ void scan2_kernel(int nb, int N, int E) {
    __shared__ int sh[128];
    int t = threadIdx.x;
    int v = (t < nb) ? g_bsum[t] : 0;
    sh[t] = v;
    __syncthreads();
    #pragma unroll
    for (int off = 1; off < 128; off <<= 1) {
        int u = (t >= off) ? sh[t - off] : 0;
        __syncthreads();
        sh[t] += u;
        __syncthreads();
    }
    if (t < nb) g_bsum[t] = sh[t] - v;
    if (t == 0) g_off[N] = E;
}

__global__ void scan3_kernel(int N) {
    __shared__ int sh[1024];
    int t = threadIdx.x;
    int i = blockIdx.x * 1024 + t;
    int v = (i < N) ? g_deg[i] : 0;
    sh[t] = v;
    __syncthreads();
    #pragma unroll
    for (int off = 1; off < 1024; off <<= 1) {
        int u = (t >= off) ? sh[t - off] : 0;
        __syncthreads();
        sh[t] += u;
        __syncthreads();
    }
    if (i < N) {
        int excl = g_bsum[blockIdx.x] + sh[t] - v;
        g_off[i]    = excl;
        g_cursor[i] = excl;
    }
}

__global__ void scatter_kernel(const void* esrc, const void* edst,
                               const float* __restrict__ ew, int E) {
    int is64 = g_is64;
    for (int i = blockIdx.x * blockDim.x + threadIdx.x; i < E;
         i += gridDim.x * blockDim.x) {
        int s = load_idx(esrc, i, is64);
        int d = load_idx(edst, i, is64);
        int pos = atomicAdd(&g_cursor[d], 1);
        g_csr_src[pos] = s;
        g_csr_w[pos]   = ew[i];
    }
}

// ---------------------------------------------------------------------------
// W -> fp16 (once per launch; 16K elements)
// ---------------------------------------------------------------------------
__global__ void convw_kernel(const float* __restrict__ W) {
    int i = blockIdx.x * blockDim.x + threadIdx.x;
    if (i < D * D) g_Wh[i] = __float2half(W[i]);
}

// ---------------------------------------------------------------------------
// Fused LayerNorm + Linear via HMMA (mma.sync m16n8k16 f16->f32).
//   block = 128 nodes, 256 threads (8 warps); warp w owns rows w*16..w*16+15.
//   A smem: LN(X) fp16 [128][AST] row-major (k contiguous).
//   B smem: W fp16 [128 o][AST] (k contiguous) == col-major B for .row.col.
// ---------------------------------------------------------------------------
#define AST 136                       // halves per row (272B, ldsm conflict-free)
#define MMA_SMEM (2 * D * AST * 2 + 512)

__device__ __forceinline__ uint32_t sptr(const void* p) {
    return (uint32_t)__cvta_generic_to_shared(p);
}

__device__ __forceinline__ void ldsm_x4(uint32_t& r0, uint32_t& r1,
                                        uint32_t& r2, uint32_t& r3,
                                        uint32_t addr) {
    asm volatile("ldmatrix.sync.aligned.m8n8.x4.shared.b16 {%0,%1,%2,%3}, [%4];"
                 : "=r"(r0), "=r"(r1), "=r"(r2), "=r"(r3) : "r"(addr));
}

__device__ __forceinline__ void ldsm_x2(uint32_t& r0, uint32_t& r1,
                                        uint32_t addr) {
    asm volatile("ldmatrix.sync.aligned.m8n8.x2.shared.b16 {%0,%1}, [%2];"
                 : "=r"(r0), "=r"(r1) : "r"(addr));
}

__device__ __forceinline__ void mma16816(float* c, uint32_t a0, uint32_t a1,
                                         uint32_t a2, uint32_t a3,
                                         uint32_t b0, uint32_t b1) {
    asm volatile(
        "mma.sync.aligned.m16n8k16.row.col.f32.f16.f16.f32 "
        "{%0,%1,%2,%3}, {%4,%5,%6,%7}, {%8,%9}, {%0,%1,%2,%3};"
        : "+f"(c[0]), "+f"(c[1]), "+f"(c[2]), "+f"(c[3])
        : "r"(a0), "r"(a1), "r"(a2), "r"(a3), "r"(b0), "r"(b1));
}

__global__ __launch_bounds__(256, 2)
void ln_mma_kernel(const float* __restrict__ X,
                   const float* __restrict__ gamma,
                   const float* __restrict__ beta,
                   const float* __restrict__ bias,
                   int N) {
    extern __shared__ __half smh[];
    __half* Ash = smh;                     // [128][AST]
    __half* Wsh = smh + D * AST;           // [128][AST]
    float*  bsh = (float*)(Wsh + D * AST); // [128]

    const int tid  = threadIdx.x;
    const int lane = tid & 31;
    const int w    = tid >> 5;
    const int n0   = blockIdx.x * 128;

    // ---- load W fp16 into smem (2048 uint4) + bias ----
    {
        const uint4* src = (const uint4*)g_Wh;
        for (int i = tid; i < 2048; i += 256) {
            int row = i >> 4, col = i & 15;
            *(uint4*)(Wsh + row * AST + col * 8) = src[i];
        }
        if (tid < D) bsh[tid] = bias[tid];
    }

    // ---- LayerNorm 16 rows per warp -> fp16 A tile ----
    const float4 g4  = ((const float4*)gamma)[lane];
    const float4 be4 = ((const float4*)beta)[lane];
    #pragma unroll 4
    for (int i = 0; i < 16; ++i) {
        int r = w * 16 + i;
        int n = n0 + r;
        float4 x = make_float4(0.f, 0.f, 0.f, 0.f);
        if (n < N) x = ((const float4*)X)[(size_t)n * 32 + lane];
        float s  = x.x + x.y + x.z + x.w;
        float ss = x.x * x.x + x.y * x.y + x.z * x.z + x.w * x.w;
        #pragma unroll
        for (int off = 16; off > 0; off >>= 1) {
            s  += __shfl_xor_sync(0xFFFFFFFFu, s,  off);
            ss += __shfl_xor_sync(0xFFFFFFFFu, ss, off);
        }
        float mu  = s * (1.f / 128.f);
        float var = ss * (1.f / 128.f) - mu * mu;
        float rr  = rsqrtf(var + LN_EPS);
        __half2 p0 = __floats2half2_rn((x.x - mu) * rr * g4.x + be4.x,
                                       (x.y - mu) * rr * g4.y + be4.y);
        __half2 p1 = __floats2half2_rn((x.z - mu) * rr * g4.z + be4.z,
                                       (x.w - mu) * rr * g4.w + be4.w);
        uint2 u;
        u.x = *(const unsigned*)&p0;
        u.y = *(const unsigned*)&p1;
        *(uint2*)(Ash + r * AST + lane * 4) = u;
    }
    __syncthreads();

    // ---- MMA: warp w computes rows w*16..+15, all 128 output cols ----
    float acc[16][4];
    {
        int cb = (lane & 3) * 2;
        #pragma unroll
        for (int nt = 0; nt < 16; ++nt) {
            float b0v = bsh[nt * 8 + cb];
            float b1v = bsh[nt * 8 + cb + 1];
            acc[nt][0] = b0v; acc[nt][1] = b1v;
            acc[nt][2] = b0v; acc[nt][3] = b1v;
        }
    }

    const uint32_t a_base = sptr(Ash + (w * 16 + (lane & 15)) * AST + (lane >> 4) * 8);
    const uint32_t b_base = sptr(Wsh + (lane & 7) * AST + ((lane & 8) ? 8 : 0));

    #pragma unroll
    for (int k = 0; k < 8; ++k) {
        uint32_t a0, a1, a2, a3;
        ldsm_x4(a0, a1, a2, a3, a_base + k * 32);   // 16 halves = 32B per k-step
        #pragma unroll
        for (int nt = 0; nt < 16; ++nt) {
            uint32_t b0, b1;
            ldsm_x2(b0, b1, b_base + nt * 8 * AST * 2 + k * 32);
            mma16816(acc[nt], a0, a1, a2, a3, b0, b1);
        }
    }
    __syncthreads();   // done reading Ash; reuse as staging

    // ---- stage C (fp16) into own A rows, then coalesced copy to g_H ----
    {
        int cb = (lane & 3) * 2;
        int r0 = w * 16 + (lane >> 2);
        #pragma unroll
        for (int nt = 0; nt < 16; ++nt) {
            *(__half2*)(Ash + r0 * AST + nt * 8 + cb) =
                __floats2half2_rn(acc[nt][0], acc[nt][1]);
            *(__half2*)(Ash + (r0 + 8) * AST + nt * 8 + cb) =
                __floats2half2_rn(acc[nt][2], acc[nt][3]);
        }
    }
    __syncwarp();

    uint4* H4g = (uint4*)g_H;   // 16 uint4 per row
    #pragma unroll
    for (int i = 0; i < 16; i += 2) {
        int r = w * 16 + i + (lane >> 4);   // lanes 0-15 row i, 16-31 row i+1
        int c = lane & 15;
        int n = n0 + r;
        if (n < N)
            H4g[(size_t)n * 16 + c] = *(const uint4*)(Ash + r * AST + c * 8);
    }
}

// ---------------------------------------------------------------------------
// CSR aggregation (fp16 gather), fused with relu + residual.
// ---------------------------------------------------------------------------
__global__ __launch_bounds__(256)
void agg_kernel(const float* __restrict__ X, float* __restrict__ out, int N) {
    const int w    = (blockIdx.x * blockDim.x + threadIdx.x) >> 5;
    const int lane = threadIdx.x & 31;
    if (w >= N) return;

    const int beg = g_off[w];
    const int end = g_off[w + 1];
    const uint2* H2 = (const uint2*)g_H;

    float4 acc = make_float4(0.f, 0.f, 0.f, 0.f);

    for (int j0 = beg; j0 < end; j0 += 32) {
        const int j = j0 + lane;
        int   s  = 0;
        float ww = 0.f;
        if (j < end) { s = __ldg(&g_csr_src[j]); ww = __ldg(&g_csr_w[j]); }
        const int cnt = min(32, end - j0);

        int k = 0;
        for (; k + 4 <= cnt; k += 4) {
            int   s0 = __shfl_sync(0xFFFFFFFFu, s,  k);
            int   s1 = __shfl_sync(0xFFFFFFFFu, s,  k + 1);
            int   s2 = __shfl_sync(0xFFFFFFFFu, s,  k + 2);
            int   s3 = __shfl_sync(0xFFFFFFFFu, s,  k + 3);
            float w0 = __shfl_sync(0xFFFFFFFFu, ww, k);
            float w1 = __shfl_sync(0xFFFFFFFFu, ww, k + 1);
            float w2 = __shfl_sync(0xFFFFFFFFu, ww, k + 2);
            float w3 = __shfl_sync(0xFFFFFFFFu, ww, k + 3);
            uint2 u0 = H2[(size_t)s0 * 32 + lane];
            uint2 u1 = H2[(size_t)s1 * 32 + lane];
            uint2 u2 = H2[(size_t)s2 * 32 + lane];
            uint2 u3 = H2[(size_t)s3 * 32 + lane];
            float2 a0 = __half22float2(*(const __half2*)&u0.x);
            float2 b0 = __half22float2(*(const __half2*)&u0.y);
            float2 a1 = __half22float2(*(const __half2*)&u1.x);
            float2 b1 = __half22float2(*(const __half2*)&u1.y);
            float2 a2 = __half22float2(*(const __half2*)&u2.x);
            float2 b2 = __half22float2(*(const __half2*)&u2.y);
            float2 a3 = __half22float2(*(const __half2*)&u3.x);
            float2 b3 = __half22float2(*(const __half2*)&u3.y);
            acc.x += w0 * a0.x; acc.y += w0 * a0.y; acc.z += w0 * b0.x; acc.w += w0 * b0.y;
            acc.x += w1 * a1.x; acc.y += w1 * a1.y; acc.z += w1 * b1.x; acc.w += w1 * b1.y;
            acc.x += w2 * a2.x; acc.y += w2 * a2.y; acc.z += w2 * b2.x; acc.w += w2 * b2.y;
            acc.x += w3 * a3.x; acc.y += w3 * a3.y; acc.z += w3 * b3.x; acc.w += w3 * b3.y;
        }
        for (; k < cnt; ++k) {
            int   sk = __shfl_sync(0xFFFFFFFFu, s,  k);
            float wk = __shfl_sync(0xFFFFFFFFu, ww, k);
            uint2 u = H2[(size_t)sk * 32 + lane];
            float2 a = __half22float2(*(const __half2*)&u.x);
            float2 b = __half22float2(*(const __half2*)&u.y);
            acc.x += wk * a.x; acc.y += wk * a.y;
            acc.z += wk * b.x; acc.w += wk * b.y;
        }
    }

    float4 x = ((const float4*)X)[(size_t)w * 32 + lane];
    float4 o;
    o.x = fmaxf(acc.x, 0.f) + x.x;
    o.y = fmaxf(acc.y, 0.f) + x.y;
    o.z = fmaxf(acc.z, 0.f) + x.z;
    o.w = fmaxf(acc.w, 0.f) + x.w;
    ((float4*)out)[(size_t)w * 32 + lane] = o;
}

// ---------------------------------------------------------------------------
// inputs: 0:X 1:edge_src 2:edge_dst 3:edge_w 4:ln_gamma 5:ln_beta 6:W 7:b
// ---------------------------------------------------------------------------
extern "C" void kernel_launch(void* const* d_in, const int* in_sizes, int n_in,
                              void* d_out, int out_size) {
    const float* X     = (const float*)d_in[0];
    const void*  esrc  = d_in[1];
    const void*  edst  = d_in[2];
    const float* ew    = (const float*)d_in[3];
    const float* gamma = (const float*)d_in[4];
    const float* beta  = (const float*)d_in[5];
    const float* W     = (const float*)d_in[6];
    const float* bias  = (const float*)d_in[7];
    float* out = (float*)d_out;

    const int N  = in_sizes[0] / D;
    const int E  = in_sizes[1];
    const int NB = (N + 1023) / 1024;

    // 1. probes / conversions
    detect_kernel<<<1, 256>>>(esrc, E);
    convw_kernel<<<64, 256>>>(W);

    // 2. CSR build (by destination)
    zero_deg_kernel<<<(N + 256) / 256, 256>>>(N);
    hist_kernel<<<2048, 256>>>(edst, E);
    scan1_kernel<<<NB, 1024>>>(N);
    scan2_kernel<<<1, 128>>>(NB, N, E);
    scan3_kernel<<<NB, 1024>>>(N);
    scatter_kernel<<<2048, 256>>>(esrc, edst, ew, E);

    // 3. fused LN + Linear via tensor cores (H in fp16)
    cudaFuncSetAttribute(ln_mma_kernel,
                         cudaFuncAttributeMaxDynamicSharedMemorySize,
                         MMA_SMEM);
    ln_mma_kernel<<<(N + 127) / 128, 256, MMA_SMEM>>>(X, gamma, beta, bias, N);

    // 4. CSR aggregation fused with relu + residual
    agg_kernel<<<(N + 7) / 8, 256>>>(X, out, N);
}